// round 2
// baseline (speedup 1.0000x reference)
#include <cuda_runtime.h>
#include <cuda_fp16.h>
#include <cstdint>

// ---------------- problem dims ----------------
#define BATCH 4096
#define DIN   4096
#define DOUT  4096

// K-chunk per pipeline stage (fp16 elements): 64 -> 128B row = full XOR-swizzle atom
#define KCHUNK   64
#define NITER    (DIN / KCHUNK)   // 64
#define NSTAGE   4

// fp16 scratch: x*D and the materialized block-circulant matrix A
__device__ __half gXh[(size_t)BATCH * DIN];
__device__ __half gAh[(size_t)DOUT * DIN];

// ---------------- PTX helpers ----------------
static __device__ __forceinline__ uint32_t smem_u32(const void* p) {
    uint32_t a;
    asm("{ .reg .u64 t; cvta.to.shared.u64 t, %1; cvt.u32.u64 %0, t; }"
        : "=r"(a) : "l"(p));
    return a;
}

#define CP_ASYNC_16(dst, src) \
    asm volatile("cp.async.cg.shared.global [%0], [%1], 16;" \
                 :: "r"(dst), "l"(src) : "memory")
#define CP_COMMIT() asm volatile("cp.async.commit_group;" ::: "memory")
#define CP_WAIT3()  asm volatile("cp.async.wait_group 3;" ::: "memory")

#define LDMATRIX_X4(r0, r1, r2, r3, addr) \
    asm volatile("ldmatrix.sync.aligned.m8n8.x4.shared.b16 {%0,%1,%2,%3}, [%4];" \
                 : "=r"(r0), "=r"(r1), "=r"(r2), "=r"(r3) : "r"(addr))

static __device__ __forceinline__ void mma16816(float* c, const uint32_t* a,
                                                uint32_t b0, uint32_t b1) {
    asm volatile(
        "mma.sync.aligned.m16n8k16.row.col.f32.f16.f16.f32 "
        "{%0,%1,%2,%3}, {%4,%5,%6,%7}, {%8,%9}, {%0,%1,%2,%3};"
        : "+f"(c[0]), "+f"(c[1]), "+f"(c[2]), "+f"(c[3])
        : "r"(a[0]), "r"(a[1]), "r"(a[2]), "r"(a[3]), "r"(b0), "r"(b1));
}

// ---------------- prep kernels ----------------
// Xh[b,q] = fp16( x[b,q] * D[q] )
__global__ void prep_x_kernel(const float* __restrict__ x, const float* __restrict__ D) {
    int idx = blockIdx.x * blockDim.x + threadIdx.x;   // one float4 per thread
    float4 xv = reinterpret_cast<const float4*>(x)[idx];
    int c4 = idx & (DIN / 4 - 1);
    float4 dv = reinterpret_cast<const float4*>(D)[c4];
    __half2 h01 = __floats2half2_rn(xv.x * dv.x, xv.y * dv.y);
    __half2 h23 = __floats2half2_rn(xv.z * dv.z, xv.w * dv.w);
    uint2 pack;
    pack.x = *reinterpret_cast<uint32_t*>(&h01);
    pack.y = *reinterpret_cast<uint32_t*>(&h23);
    reinterpret_cast<uint2*>(gXh)[idx] = pack;
}

// Ah[p,q] = fp16( W[p>>7, q>>7, ((q&127)-(p&127)) & 127] )
__global__ void prep_a_kernel(const float* __restrict__ W) {
    __shared__ float wsh[32 * 128];     // W[i, :, :]  (16 KB)
    int p = blockIdx.x;
    int i = p >> 7, t = p & 127;
    for (int idx = threadIdx.x; idx < 32 * 128; idx += blockDim.x)
        wsh[idx] = W[(size_t)i * 32 * 128 + idx];
    __syncthreads();
    for (int q2 = threadIdx.x; q2 < DIN / 2; q2 += blockDim.x) {
        int q = q2 * 2;
        int j = q >> 7, s = q & 127;
        float a = wsh[j * 128 + ((s - t) & 127)];
        float b = wsh[j * 128 + ((s + 1 - t) & 127)];
        reinterpret_cast<__half2*>(gAh)[(size_t)p * (DIN / 2) + q2] =
            __floats2half2_rn(a, b);
    }
}

// ---------------- GEMM kernel ----------------
// Per-CTA 128x128 output tile: out = Xh @ Ah^T + bias
// 8 warps (2 M x 4 N), warp tile 64x32, mma.sync m16n8k16 f16->f32.
#define STAGE_BYTES 32768               // A tile 16KB + B tile 16KB
#define SMEM_BYTES  (1024 + NSTAGE * STAGE_BYTES)

// cp.async one 128x64 fp16 tile with XOR-8 swizzle (16B chunk c -> c^(r&7))
static __device__ __forceinline__ void load_tile(uint32_t sbase, const __half* gbase,
                                                 int row0, int k0, int tid) {
    const char* gb = reinterpret_cast<const char*>(gbase);
#pragma unroll
    for (int ch = tid; ch < 1024; ch += 256) {
        int r = ch >> 3, c = ch & 7;
        uint32_t dst = sbase + (uint32_t)(r * 128 + ((c ^ (r & 7)) << 4));
        const void* src = gb + ((size_t)(row0 + r) * DIN + k0) * 2 + (c << 4);
        CP_ASYNC_16(dst, src);
    }
}

__global__ void __launch_bounds__(256, 1)
gemm_kernel(const float* __restrict__ bias, float* __restrict__ out) {
    extern __shared__ char smem_raw[];
    uint32_t sb = (smem_u32(smem_raw) + 1023u) & ~1023u;
    const uint32_t tiles = sb;

    int tid = threadIdx.x, wid = tid >> 5, lane = tid & 31;
    int m0 = blockIdx.y * 128, n0 = blockIdx.x * 128;
    int warpM = wid & 1, warpN = wid >> 1;          // 2 x 4 warps

    // --- precompute ldmatrix row offsets (swizzle applied per k-step) ---
    int g = lane >> 3, rr = lane & 7;
    // A: x4 covers one m16 x k16 frag; groups: (m0-7,k0-7) (m8-15,k0-7) (m0-7,k8-15) (m8-15,k8-15)
    uint32_t aRowOff[4]; int aR7[4]; int cbitA = g >> 1;
    // B: x4 covers two n8-tiles x k16; groups: (n0-7,k0-7) (n0-7,k8-15) (n8-15,k0-7) (n8-15,k8-15)
    uint32_t bRowOff[2]; int bR7[2]; int cbitB = g & 1;
#pragma unroll
    for (int mt = 0; mt < 4; mt++) {
        int r = warpM * 64 + mt * 16 + ((g & 1) << 3) + rr;
        aRowOff[mt] = (uint32_t)(r * 128); aR7[mt] = r & 7;
    }
#pragma unroll
    for (int nt2 = 0; nt2 < 2; nt2++) {
        int r = warpN * 32 + nt2 * 16 + ((g >> 1) << 3) + rr;
        bRowOff[nt2] = (uint32_t)(r * 128); bR7[nt2] = r & 7;
    }

    float acc[4][4][4];
#pragma unroll
    for (int mt = 0; mt < 4; mt++)
#pragma unroll
        for (int nt = 0; nt < 4; nt++)
#pragma unroll
            for (int k = 0; k < 4; k++) acc[mt][nt][k] = 0.f;

    // --- prologue: fill all stages ---
#pragma unroll
    for (int s = 0; s < NSTAGE; s++) {
        load_tile(tiles + s * STAGE_BYTES,         gXh, m0, s * KCHUNK, tid);
        load_tile(tiles + s * STAGE_BYTES + 16384, gAh, n0, s * KCHUNK, tid);
        CP_COMMIT();
    }

#pragma unroll 1
    for (int it = 0; it < NITER; it++) {
        int s = it & (NSTAGE - 1);
        uint32_t sA = tiles + s * STAGE_BYTES;
        uint32_t sB = sA + 16384;

        CP_WAIT3();            // this thread's loads for iter `it` are done
        __syncthreads();       // everyone's loads are done

#pragma unroll
        for (int ks = 0; ks < 4; ks++) {
            uint32_t a[4][4], b[2][4];
#pragma unroll
            for (int mt = 0; mt < 4; mt++) {
                uint32_t addr = sA + aRowOff[mt] +
                                (uint32_t)((((ks << 1) + cbitA) ^ aR7[mt]) << 4);
                LDMATRIX_X4(a[mt][0], a[mt][1], a[mt][2], a[mt][3], addr);
            }
#pragma unroll
            for (int nt2 = 0; nt2 < 2; nt2++) {
                uint32_t addr = sB + bRowOff[nt2] +
                                (uint32_t)((((ks << 1) + cbitB) ^ bR7[nt2]) << 4);
                LDMATRIX_X4(b[nt2][0], b[nt2][1], b[nt2][2], b[nt2][3], addr);
            }
#pragma unroll
            for (int mt = 0; mt < 4; mt++)
#pragma unroll
                for (int nt = 0; nt < 4; nt++)
                    mma16816(acc[mt][nt], a[mt],
                             b[nt >> 1][(nt & 1) << 1], b[nt >> 1][((nt & 1) << 1) + 1]);
        }

        __syncthreads();       // all warps done reading stage s before overwrite
        if (it + NSTAGE < NITER) {
            load_tile(sA, gXh, m0, (it + NSTAGE) * KCHUNK, tid);
            load_tile(sB, gAh, n0, (it + NSTAGE) * KCHUNK, tid);
        }
        CP_COMMIT();           // always commit to keep group counts uniform
    }

    // --- epilogue: direct register -> global with bias ---
    float2 bv[4];
#pragma unroll
    for (int nt = 0; nt < 4; nt++) {
        int col = n0 + warpN * 32 + nt * 8 + ((lane & 3) << 1);
        bv[nt] = __ldg(reinterpret_cast<const float2*>(bias + col));
    }
#pragma unroll
    for (int mt = 0; mt < 4; mt++) {
        int r0 = m0 + warpM * 64 + mt * 16 + (lane >> 2);
#pragma unroll
        for (int nt = 0; nt < 4; nt++) {
            int col = n0 + warpN * 32 + nt * 8 + ((lane & 3) << 1);
            float2 v0, v1;
            v0.x = acc[mt][nt][0] + bv[nt].x;
            v0.y = acc[mt][nt][1] + bv[nt].y;
            v1.x = acc[mt][nt][2] + bv[nt].x;
            v1.y = acc[mt][nt][3] + bv[nt].y;
            *reinterpret_cast<float2*>(out + (size_t)r0 * DOUT + col) = v0;
            *reinterpret_cast<float2*>(out + (size_t)(r0 + 8) * DOUT + col) = v1;
        }
    }
}

// ---------------- launch ----------------
extern "C" void kernel_launch(void* const* d_in, const int* in_sizes, int n_in,
                              void* d_out, int out_size) {
    const float* x    = (const float*)d_in[0];
    const float* W    = (const float*)d_in[1];
    const float* D    = (const float*)d_in[2];
    const float* bias = (const float*)d_in[3];
    float* out = (float*)d_out;

    cudaFuncSetAttribute(gemm_kernel, cudaFuncAttributeMaxDynamicSharedMemorySize,
                         SMEM_BYTES);

    prep_x_kernel<<<(BATCH * DIN / 4) / 256, 256>>>(x, D);
    prep_a_kernel<<<DOUT, 256>>>(W);
    gemm_kernel<<<dim3(DOUT / 128, BATCH / 128), 256, SMEM_BYTES>>>(bias, out);
}

// round 4
// speedup vs baseline: 1.0238x; 1.0238x over previous
#include <cuda_runtime.h>
#include <cuda_fp16.h>
#include <cstdint>

// ---------------- problem dims ----------------
#define BATCH 4096
#define DIN   4096
#define DOUT  4096

#define KCHUNK   64
#define NITER    (DIN / KCHUNK)   // 64
#define NSTAGE   4

// CTA tile 128(M) x 256(N), 8 warps (2Mx4N), warp tile 64x64
#define CTA_M 128
#define CTA_N 256

// fp16 scratch: x*D and the materialized block-circulant matrix A
__device__ __half gXh[(size_t)BATCH * DIN];
__device__ __half gAh[(size_t)DOUT * DIN];

// ---------------- PTX helpers ----------------
static __device__ __forceinline__ uint32_t smem_u32(const void* p) {
    uint32_t a;
    asm("{ .reg .u64 t; cvta.to.shared.u64 t, %1; cvt.u32.u64 %0, t; }"
        : "=r"(a) : "l"(p));
    return a;
}

#define CP_ASYNC_16(dst, src) \
    asm volatile("cp.async.cg.shared.global [%0], [%1], 16;" \
                 :: "r"(dst), "l"(src) : "memory")
#define CP_COMMIT() asm volatile("cp.async.commit_group;" ::: "memory")
#define CP_WAIT2()  asm volatile("cp.async.wait_group 2;" ::: "memory")

#define LDMATRIX_X4(r0, r1, r2, r3, addr) \
    asm volatile("ldmatrix.sync.aligned.m8n8.x4.shared.b16 {%0,%1,%2,%3}, [%4];" \
                 : "=r"(r0), "=r"(r1), "=r"(r2), "=r"(r3) : "r"(addr))

static __device__ __forceinline__ void mma16816(float* c, const uint32_t* a,
                                                uint32_t b0, uint32_t b1) {
    asm volatile(
        "mma.sync.aligned.m16n8k16.row.col.f32.f16.f16.f32 "
        "{%0,%1,%2,%3}, {%4,%5,%6,%7}, {%8,%9}, {%0,%1,%2,%3};"
        : "+f"(c[0]), "+f"(c[1]), "+f"(c[2]), "+f"(c[3])
        : "r"(a[0]), "r"(a[1]), "r"(a[2]), "r"(a[3]), "r"(b0), "r"(b1));
}

// ---------------- prep kernels ----------------
__global__ void prep_x_kernel(const float* __restrict__ x, const float* __restrict__ D) {
    int idx = blockIdx.x * blockDim.x + threadIdx.x;   // one float4 per thread
    float4 xv = reinterpret_cast<const float4*>(x)[idx];
    int c4 = idx & (DIN / 4 - 1);
    float4 dv = reinterpret_cast<const float4*>(D)[c4];
    __half2 h01 = __floats2half2_rn(xv.x * dv.x, xv.y * dv.y);
    __half2 h23 = __floats2half2_rn(xv.z * dv.z, xv.w * dv.w);
    uint2 pack;
    pack.x = *reinterpret_cast<uint32_t*>(&h01);
    pack.y = *reinterpret_cast<uint32_t*>(&h23);
    reinterpret_cast<uint2*>(gXh)[idx] = pack;
}

// Ah[p,q] = fp16( W[p>>7, q>>7, ((q&127)-(p&127)) & 127] )
__global__ void prep_a_kernel(const float* __restrict__ W) {
    __shared__ float wsh[32 * 128];     // W[i, :, :]  (16 KB)
    int p = blockIdx.x;
    int i = p >> 7, t = p & 127;
    for (int idx = threadIdx.x; idx < 32 * 128; idx += blockDim.x)
        wsh[idx] = W[(size_t)i * 32 * 128 + idx];
    __syncthreads();
    for (int q2 = threadIdx.x; q2 < DIN / 2; q2 += blockDim.x) {
        int q = q2 * 2;
        int j = q >> 7, s = q & 127;
        float a = wsh[j * 128 + ((s - t) & 127)];
        float b = wsh[j * 128 + ((s + 1 - t) & 127)];
        reinterpret_cast<__half2*>(gAh)[(size_t)p * (DIN / 2) + q2] =
            __floats2half2_rn(a, b);
    }
}

// ---------------- GEMM kernel ----------------
#define A_TILE_BYTES (CTA_M * 128)               // 16 KB
#define B_TILE_BYTES (CTA_N * 128)               // 32 KB
#define STAGE_BYTES  (A_TILE_BYTES + B_TILE_BYTES)
#define SMEM_BYTES   (1024 + NSTAGE * STAGE_BYTES)

// cp.async a NROWSx64 fp16 tile with XOR-8 swizzle (16B chunk c -> c^(r&7))
template <int NROWS>
static __device__ __forceinline__ void load_tile(uint32_t sbase, const __half* gbase,
                                                 int row0, int k0, int tid) {
    const char* gb = reinterpret_cast<const char*>(gbase);
#pragma unroll
    for (int ch = tid; ch < NROWS * 8; ch += 256) {
        int r = ch >> 3, c = ch & 7;
        uint32_t dst = sbase + (uint32_t)(r * 128 + ((c ^ (r & 7)) << 4));
        const void* src = gb + ((size_t)(row0 + r) * DIN + k0) * 2 + (c << 4);
        CP_ASYNC_16(dst, src);
    }
}

__global__ void __launch_bounds__(256, 1)
gemm_kernel(const float* __restrict__ bias, float* __restrict__ out) {
    extern __shared__ char smem_raw[];
    uint32_t sb = (smem_u32(smem_raw) + 1023u) & ~1023u;
    const uint32_t tiles = sb;

    int tid = threadIdx.x, wid = tid >> 5, lane = tid & 31;
    int m0 = blockIdx.y * CTA_M, n0 = blockIdx.x * CTA_N;
    int warpM = wid & 1, warpN = wid >> 1;          // 2 x 4 warps, warp tile 64x64

    // --- ldmatrix row offsets (swizzle column applied per k-step) ---
    int g = lane >> 3, rr = lane & 7;
    // A x4 frag (m16 x k16): groups (m0-7,k0-7)(m8-15,k0-7)(m0-7,k8-15)(m8-15,k8-15)
    uint32_t aRowOff[4]; int aR7[4]; int cbitA = g >> 1;
    // B x4 frag (n16 x k16): groups (n0-7,k0-7)(n0-7,k8-15)(n8-15,k0-7)(n8-15,k8-15)
    uint32_t bRowOff[4]; int bR7[4]; int cbitB = g & 1;
#pragma unroll
    for (int mt = 0; mt < 4; mt++) {
        int r = warpM * 64 + mt * 16 + ((g & 1) << 3) + rr;
        aRowOff[mt] = (uint32_t)(r * 128); aR7[mt] = r & 7;
    }
#pragma unroll
    for (int nt2 = 0; nt2 < 4; nt2++) {
        int r = warpN * 64 + nt2 * 16 + ((g >> 1) << 3) + rr;
        bRowOff[nt2] = (uint32_t)(r * 128); bR7[nt2] = r & 7;
    }

    float acc[4][8][4];
#pragma unroll
    for (int mt = 0; mt < 4; mt++)
#pragma unroll
        for (int nt = 0; nt < 8; nt++)
#pragma unroll
            for (int k = 0; k < 4; k++) acc[mt][nt][k] = 0.f;

    // --- prologue: fill NSTAGE-1 stages ---
#pragma unroll
    for (int s = 0; s < NSTAGE - 1; s++) {
        load_tile<CTA_M>(tiles + s * STAGE_BYTES,                gXh, m0, s * KCHUNK, tid);
        load_tile<CTA_N>(tiles + s * STAGE_BYTES + A_TILE_BYTES, gAh, n0, s * KCHUNK, tid);
        CP_COMMIT();
    }

#pragma unroll 1
    for (int it = 0; it < NITER; it++) {
        int s = it & (NSTAGE - 1);
        uint32_t sA = tiles + s * STAGE_BYTES;
        uint32_t sB = sA + A_TILE_BYTES;

        CP_WAIT2();            // stage `it` complete (<=2 groups pending)
        __syncthreads();       // all warps see it; stage (it-1)%4 fully consumed

        // issue next stage's loads FIRST so cp.async overlaps the MMA burst
        if (it + NSTAGE - 1 < NITER) {
            int sl = (it + NSTAGE - 1) & (NSTAGE - 1);
            uint32_t dA = tiles + sl * STAGE_BYTES;
            load_tile<CTA_M>(dA,                gXh, m0, (it + NSTAGE - 1) * KCHUNK, tid);
            load_tile<CTA_N>(dA + A_TILE_BYTES, gAh, n0, (it + NSTAGE - 1) * KCHUNK, tid);
        }
        CP_COMMIT();           // unconditional: keep group counts uniform

#pragma unroll
        for (int ks = 0; ks < 4; ks++) {
            uint32_t a[4][4], b[4][4];
#pragma unroll
            for (int mt = 0; mt < 4; mt++) {
                uint32_t addr = sA + aRowOff[mt] +
                                (uint32_t)((((ks << 1) + cbitA) ^ aR7[mt]) << 4);
                LDMATRIX_X4(a[mt][0], a[mt][1], a[mt][2], a[mt][3], addr);
            }
#pragma unroll
            for (int nt2 = 0; nt2 < 4; nt2++) {
                uint32_t addr = sB + bRowOff[nt2] +
                                (uint32_t)((((ks << 1) + cbitB) ^ bR7[nt2]) << 4);
                LDMATRIX_X4(b[nt2][0], b[nt2][1], b[nt2][2], b[nt2][3], addr);
            }
#pragma unroll
            for (int mt = 0; mt < 4; mt++)
#pragma unroll
                for (int nt = 0; nt < 8; nt++)
                    mma16816(acc[mt][nt], a[mt],
                             b[nt >> 1][(nt & 1) << 1], b[nt >> 1][((nt & 1) << 1) + 1]);
        }
    }

    // --- epilogue: registers -> global with bias ---
    float2 bv[8];
#pragma unroll
    for (int nt = 0; nt < 8; nt++) {
        int col = n0 + warpN * 64 + nt * 8 + ((lane & 3) << 1);
        bv[nt] = __ldg(reinterpret_cast<const float2*>(bias + col));
    }
#pragma unroll
    for (int mt = 0; mt < 4; mt++) {
        int r0 = m0 + warpM * 64 + mt * 16 + (lane >> 2);
#pragma unroll
        for (int nt = 0; nt < 8; nt++) {
            int col = n0 + warpN * 64 + nt * 8 + ((lane & 3) << 1);
            float2 v0, v1;
            v0.x = acc[mt][nt][0] + bv[nt].x;
            v0.y = acc[mt][nt][1] + bv[nt].y;
            v1.x = acc[mt][nt][2] + bv[nt].x;
            v1.y = acc[mt][nt][3] + bv[nt].y;
            *reinterpret_cast<float2*>(out + (size_t)r0 * DOUT + col) = v0;
            *reinterpret_cast<float2*>(out + (size_t)(r0 + 8) * DOUT + col) = v1;
        }
    }
}

// ---------------- launch ----------------
extern "C" void kernel_launch(void* const* d_in, const int* in_sizes, int n_in,
                              void* d_out, int out_size) {
    const float* x    = (const float*)d_in[0];
    const float* W    = (const float*)d_in[1];
    const float* D    = (const float*)d_in[2];
    const float* bias = (const float*)d_in[3];
    float* out = (float*)d_out;

    cudaFuncSetAttribute(gemm_kernel, cudaFuncAttributeMaxDynamicSharedMemorySize,
                         SMEM_BYTES);

    prep_x_kernel<<<(BATCH * DIN / 4) / 256, 256>>>(x, D);
    prep_a_kernel<<<DOUT, 256>>>(W);
    gemm_kernel<<<dim3(DOUT / CTA_N, BATCH / CTA_M), 256, SMEM_BYTES>>>(bias, out);
}

// round 6
// speedup vs baseline: 1.2184x; 1.1900x over previous
#include <cuda_runtime.h>
#include <cuda_fp16.h>
#include <cstdint>

// ---------------- problem dims ----------------
#define BATCH 4096
#define DIN   4096
#define DOUT  4096

#define KCHUNK   64
#define NITER    (DIN / KCHUNK)   // 64
#define NSTAGE   3

// CTA tile 128x128, 8 warps (2Mx4N), warp tile 64x32, 2 CTAs/SM
#define CTA_M 128
#define CTA_N 128

// fp16 scratch: x*D and the materialized block-circulant matrix A
__device__ __half gXh[(size_t)BATCH * DIN];
__device__ __half gAh[(size_t)DOUT * DIN];

// ---------------- PTX helpers ----------------
static __device__ __forceinline__ uint32_t smem_u32(const void* p) {
    uint32_t a;
    asm("{ .reg .u64 t; cvta.to.shared.u64 t, %1; cvt.u32.u64 %0, t; }"
        : "=r"(a) : "l"(p));
    return a;
}

#define CP_ASYNC_16(dst, src) \
    asm volatile("cp.async.cg.shared.global [%0], [%1], 16;" \
                 :: "r"(dst), "l"(src) : "memory")
#define CP_COMMIT() asm volatile("cp.async.commit_group;" ::: "memory")
#define CP_WAIT1()  asm volatile("cp.async.wait_group 1;" ::: "memory")

#define LDMATRIX_X4(r0, r1, r2, r3, addr) \
    asm volatile("ldmatrix.sync.aligned.m8n8.x4.shared.b16 {%0,%1,%2,%3}, [%4];" \
                 : "=r"(r0), "=r"(r1), "=r"(r2), "=r"(r3) : "r"(addr))

static __device__ __forceinline__ void mma16816(float* c, const uint32_t* a,
                                                uint32_t b0, uint32_t b1) {
    asm volatile(
        "mma.sync.aligned.m16n8k16.row.col.f32.f16.f16.f32 "
        "{%0,%1,%2,%3}, {%4,%5,%6,%7}, {%8,%9}, {%0,%1,%2,%3};"
        : "+f"(c[0]), "+f"(c[1]), "+f"(c[2]), "+f"(c[3])
        : "r"(a[0]), "r"(a[1]), "r"(a[2]), "r"(a[3]), "r"(b0), "r"(b1));
}

// ---------------- prep kernels ----------------
__global__ void prep_x_kernel(const float* __restrict__ x, const float* __restrict__ D) {
    int idx = blockIdx.x * blockDim.x + threadIdx.x;   // one float4 per thread
    float4 xv = reinterpret_cast<const float4*>(x)[idx];
    int c4 = idx & (DIN / 4 - 1);
    float4 dv = reinterpret_cast<const float4*>(D)[c4];
    __half2 h01 = __floats2half2_rn(xv.x * dv.x, xv.y * dv.y);
    __half2 h23 = __floats2half2_rn(xv.z * dv.z, xv.w * dv.w);
    uint2 pack;
    pack.x = *reinterpret_cast<uint32_t*>(&h01);
    pack.y = *reinterpret_cast<uint32_t*>(&h23);
    reinterpret_cast<uint2*>(gXh)[idx] = pack;
}

// Ah[p,q] = fp16( W[p>>7, q>>7, ((q&127)-(p&127)) & 127] )
__global__ void prep_a_kernel(const float* __restrict__ W) {
    __shared__ float wsh[32 * 128];     // W[i, :, :]  (16 KB)
    int p = blockIdx.x;
    int i = p >> 7, t = p & 127;
    for (int idx = threadIdx.x; idx < 32 * 128; idx += blockDim.x)
        wsh[idx] = W[(size_t)i * 32 * 128 + idx];
    __syncthreads();
    for (int q2 = threadIdx.x; q2 < DIN / 2; q2 += blockDim.x) {
        int q = q2 * 2;
        int j = q >> 7, s = q & 127;
        float a = wsh[j * 128 + ((s - t) & 127)];
        float b = wsh[j * 128 + ((s + 1 - t) & 127)];
        reinterpret_cast<__half2*>(gAh)[(size_t)p * (DIN / 2) + q2] =
            __floats2half2_rn(a, b);
    }
}

// ---------------- GEMM kernel ----------------
#define A_TILE_BYTES (CTA_M * 128)               // 16 KB
#define B_TILE_BYTES (CTA_N * 128)               // 16 KB
#define STAGE_BYTES  (A_TILE_BYTES + B_TILE_BYTES)
#define SMEM_BYTES   (NSTAGE * STAGE_BYTES)      // 96 KB -> 2 CTAs/SM

// cp.async a NROWSx64 fp16 tile with XOR-8 swizzle (16B chunk c -> c^(r&7))
template <int NROWS>
static __device__ __forceinline__ void load_tile(uint32_t sbase, const __half* gbase,
                                                 int row0, int k0, int tid) {
    const char* gb = reinterpret_cast<const char*>(gbase);
#pragma unroll
    for (int ch = tid; ch < NROWS * 8; ch += 256) {
        int r = ch >> 3, c = ch & 7;
        uint32_t dst = sbase + (uint32_t)(r * 128 + ((c ^ (r & 7)) << 4));
        const void* src = gb + ((size_t)(row0 + r) * DIN + k0) * 2 + (c << 4);
        CP_ASYNC_16(dst, src);
    }
}

__global__ void __launch_bounds__(256, 2)
gemm_kernel(const float* __restrict__ bias, float* __restrict__ out) {
    extern __shared__ char smem_raw[];
    const uint32_t tiles = smem_u32(smem_raw);   // dynamic smem is 1KB-aligned

    int tid = threadIdx.x, wid = tid >> 5, lane = tid & 31;
    int m0 = blockIdx.y * CTA_M, n0 = blockIdx.x * CTA_N;
    int warpM = wid & 1, warpN = wid >> 1;          // 2 x 4 warps, warp tile 64x32

    // --- ldmatrix row offsets (swizzle column applied per k-step) ---
    int g = lane >> 3, rr = lane & 7;
    // A x4 frag (m16 x k16): groups (m0-7,k0-7)(m8-15,k0-7)(m0-7,k8-15)(m8-15,k8-15)
    uint32_t aRowOff[4]; int aR7[4]; int cbitA = g >> 1;
    // B x4 frag (n16 x k16): groups (n0-7,k0-7)(n0-7,k8-15)(n8-15,k0-7)(n8-15,k8-15)
    uint32_t bRowOff[2]; int bR7[2]; int cbitB = g & 1;
#pragma unroll
    for (int mt = 0; mt < 4; mt++) {
        int r = warpM * 64 + mt * 16 + ((g & 1) << 3) + rr;
        aRowOff[mt] = (uint32_t)(r * 128); aR7[mt] = r & 7;
    }
#pragma unroll
    for (int nt2 = 0; nt2 < 2; nt2++) {
        int r = warpN * 32 + nt2 * 16 + ((g >> 1) << 3) + rr;
        bRowOff[nt2] = (uint32_t)(r * 128); bR7[nt2] = r & 7;
    }

    float acc[4][4][4];
#pragma unroll
    for (int mt = 0; mt < 4; mt++)
#pragma unroll
        for (int nt = 0; nt < 4; nt++)
#pragma unroll
            for (int k = 0; k < 4; k++) acc[mt][nt][k] = 0.f;

    // --- prologue: fill NSTAGE-1 stages ---
#pragma unroll
    for (int s = 0; s < NSTAGE - 1; s++) {
        load_tile<CTA_M>(tiles + s * STAGE_BYTES,                gXh, m0, s * KCHUNK, tid);
        load_tile<CTA_N>(tiles + s * STAGE_BYTES + A_TILE_BYTES, gAh, n0, s * KCHUNK, tid);
        CP_COMMIT();
    }

    int s = 0;
#pragma unroll 1
    for (int it = 0; it < NITER; it++) {
        uint32_t sA = tiles + s * STAGE_BYTES;
        uint32_t sB = sA + A_TILE_BYTES;

        CP_WAIT1();            // stage `it` complete (<=1 group pending)
        __syncthreads();       // all warps: stage it ready, stage (it+2)%3 consumed

        // issue next stage's loads FIRST so cp.async overlaps the MMA burst
        if (it + NSTAGE - 1 < NITER) {
            int sl = s + 2 >= NSTAGE ? s - 1 : s + 2;
            uint32_t dA = tiles + sl * STAGE_BYTES;
            load_tile<CTA_M>(dA,                gXh, m0, (it + NSTAGE - 1) * KCHUNK, tid);
            load_tile<CTA_N>(dA + A_TILE_BYTES, gAh, n0, (it + NSTAGE - 1) * KCHUNK, tid);
        }
        CP_COMMIT();           // unconditional: keep group counts uniform

#pragma unroll
        for (int ks = 0; ks < 4; ks++) {
            uint32_t a[4][4], b[2][4];
#pragma unroll
            for (int mt = 0; mt < 4; mt++) {
                uint32_t addr = sA + aRowOff[mt] +
                                (uint32_t)((((ks << 1) + cbitA) ^ aR7[mt]) << 4);
                LDMATRIX_X4(a[mt][0], a[mt][1], a[mt][2], a[mt][3], addr);
            }
#pragma unroll
            for (int nt2 = 0; nt2 < 2; nt2++) {
                uint32_t addr = sB + bRowOff[nt2] +
                                (uint32_t)((((ks << 1) + cbitB) ^ bR7[nt2]) << 4);
                LDMATRIX_X4(b[nt2][0], b[nt2][1], b[nt2][2], b[nt2][3], addr);
            }
#pragma unroll
            for (int mt = 0; mt < 4; mt++)
#pragma unroll
                for (int nt = 0; nt < 4; nt++)
                    mma16816(acc[mt][nt], a[mt],
                             b[nt >> 1][(nt & 1) << 1], b[nt >> 1][((nt & 1) << 1) + 1]);
        }
        s = (s + 1 == NSTAGE) ? 0 : s + 1;
    }

    // --- epilogue: registers -> global with bias ---
    float2 bv[4];
#pragma unroll
    for (int nt = 0; nt < 4; nt++) {
        int col = n0 + warpN * 32 + nt * 8 + ((lane & 3) << 1);
        bv[nt] = __ldg(reinterpret_cast<const float2*>(bias + col));
    }
#pragma unroll
    for (int mt = 0; mt < 4; mt++) {
        int r0 = m0 + warpM * 64 + mt * 16 + (lane >> 2);
#pragma unroll
        for (int nt = 0; nt < 4; nt++) {
            int col = n0 + warpN * 32 + nt * 8 + ((lane & 3) << 1);
            float2 v0, v1;
            v0.x = acc[mt][nt][0] + bv[nt].x;
            v0.y = acc[mt][nt][1] + bv[nt].y;
            v1.x = acc[mt][nt][2] + bv[nt].x;
            v1.y = acc[mt][nt][3] + bv[nt].y;
            *reinterpret_cast<float2*>(out + (size_t)r0 * DOUT + col) = v0;
            *reinterpret_cast<float2*>(out + (size_t)(r0 + 8) * DOUT + col) = v1;
        }
    }
}

// ---------------- launch ----------------
extern "C" void kernel_launch(void* const* d_in, const int* in_sizes, int n_in,
                              void* d_out, int out_size) {
    const float* x    = (const float*)d_in[0];
    const float* W    = (const float*)d_in[1];
    const float* D    = (const float*)d_in[2];
    const float* bias = (const float*)d_in[3];
    float* out = (float*)d_out;

    cudaFuncSetAttribute(gemm_kernel, cudaFuncAttributeMaxDynamicSharedMemorySize,
                         SMEM_BYTES);

    prep_x_kernel<<<(BATCH * DIN / 4) / 256, 256>>>(x, D);
    prep_a_kernel<<<DOUT, 256>>>(W);
    gemm_kernel<<<dim3(DOUT / CTA_N, BATCH / CTA_M), 256, SMEM_BYTES>>>(bias, out);
}